// round 2
// baseline (speedup 1.0000x reference)
#include <cuda_runtime.h>
#include <cstdint>
#include <cstddef>

#define Bn 128
#define Tn 2048
#define Cn 128
#define NTHR 512
#define TSTRIDE 132  // padded row stride for transposed transitions in smem

// Scratch: all forward alphas (exact fp32). __device__ global (no runtime alloc).
__device__ __align__(16) float g_alpha[(size_t)Bn * Tn * Cn];

__device__ __forceinline__ unsigned long long pack2(float lo, float hi) {
    unsigned long long r;
    asm("mov.b64 %0, {%1, %2};" : "=l"(r) : "f"(lo), "f"(hi));
    return r;
}
__device__ __forceinline__ unsigned long long add2(unsigned long long a, unsigned long long b) {
    unsigned long long r;
    asm("add.rn.f32x2 %0, %1, %2;" : "=l"(r) : "l"(a), "l"(b));
    return r;
}
__device__ __forceinline__ float lo32(unsigned long long v) {
    return __uint_as_float((unsigned)v);
}
__device__ __forceinline__ float hi32(unsigned long long v) {
    return __uint_as_float((unsigned)(v >> 32));
}

// Exact monotone float->int key: a > b (fp, no NaN) <=> fkey(a) > fkey(b) (signed int).
__device__ __forceinline__ int fkey(float f) {
    int b = __float_as_int(f);
    return b ^ ((b >> 31) & 0x7fffffff);
}

// Warp-collective argmax over 128 values (lane l holds values for indices 4l..4l+3).
// Returns the SMALLEST index achieving the exact max (matches jnp.argmax first-max).
__device__ __forceinline__ int warp_argmax4(float4 v, int l) {
    int k0 = fkey(v.x), k1 = fkey(v.y), k2 = fkey(v.z), k3 = fkey(v.w);
    int km = max(max(k0, k1), max(k2, k3));
    int wm = __reduce_max_sync(0xffffffffu, km);
    unsigned i0 = (k0 == wm) ? (unsigned)(4 * l + 0) : 0xffffffffu;
    unsigned i1 = (k1 == wm) ? (unsigned)(4 * l + 1) : 0xffffffffu;
    unsigned i2 = (k2 == wm) ? (unsigned)(4 * l + 2) : 0xffffffffu;
    unsigned i3 = (k3 == wm) ? (unsigned)(4 * l + 3) : 0xffffffffu;
    unsigned c = min(min(i0, i1), min(i2, i3));
    return (int)__reduce_min_sync(0xffffffffu, c);
}

__global__ __launch_bounds__(NTHR, 1)
void viterbi_kernel(const float* __restrict__ pot,
                    const float* __restrict__ trans,
                    float* __restrict__ out) {
    extern __shared__ float smem[];
    float* tT = smem;                       // [Cn][TSTRIDE]: tT[j*TSTRIDE + i] = trans[i][j]
    float* sb = smem + Cn * TSTRIDE;        // double-buffered alpha row, 2*Cn floats (16B aligned)

    const int b = blockIdx.x;
    const int tid = threadIdx.x;
    const int c = tid & 3;    // i-chunk
    const int j = tid >> 2;   // class handled by this thread-quad

    // ---- Build transposed transitions in smem (coalesced global reads) ----
    {
        int j0 = tid & 127;
        int r = tid >> 7;  // 0..3
        #pragma unroll
        for (int k = 0; k < 32; ++k) {
            int i = r * 32 + k;
            tT[j0 * TSTRIDE + i] = trans[i * Cn + j0];
        }
    }

    // ---- Per-thread transition registers: i = 16g + 4c + {0..3}, column j, packed ----
    unsigned long long tr2[16];
    #pragma unroll
    for (int g = 0; g < 8; ++g) {
        int i0 = 16 * g + 4 * c;
        float t0 = trans[(i0 + 0) * Cn + j];
        float t1 = trans[(i0 + 1) * Cn + j];
        float t2 = trans[(i0 + 2) * Cn + j];
        float t3 = trans[(i0 + 3) * Cn + j];
        tr2[2 * g]     = pack2(t0, t1);
        tr2[2 * g + 1] = pack2(t2, t3);
    }

    const float* potp = pot + ((size_t)b * Tn) * Cn + j;
    float* aout = g_alpha + ((size_t)b * Tn) * Cn + j;

    // ---- t = 0 ----
    float alpha = potp[0];
    if (c == 0) {
        sb[j] = alpha;
        aout[0] = alpha;
    }

    // Potentials prefetch ring (distance 4 steps)
    float pr[4];
    #pragma unroll
    for (int u = 0; u < 4; ++u) pr[u] = potp[(size_t)(1 + u) * Cn];

    __syncthreads();

    const float NEG_INF = __int_as_float(0xff800000);

    // ---- Forward: t = 1 .. T-1 ----
    int p = 0;
    for (int tb = 1; tb < Tn; tb += 4) {
        #pragma unroll
        for (int u = 0; u < 4; ++u) {
            int t = tb + u;
            if (t < Tn) {  // uniform across CTA
                float potv = pr[u];
                if (t + 4 < Tn) pr[u] = potp[(size_t)(t + 4) * Cn];

                const ulonglong2* ab = (const ulonglong2*)(sb + p * Cn);
                float m0 = NEG_INF, m1 = NEG_INF, m2 = NEG_INF, m3 = NEG_INF;
                #pragma unroll
                for (int g = 0; g < 8; ++g) {
                    ulonglong2 a = ab[4 * g + c];  // 16B: alpha[16g+4c .. +3]
                    unsigned long long s01 = add2(a.x, tr2[2 * g]);
                    unsigned long long s23 = add2(a.y, tr2[2 * g + 1]);
                    m0 = fmaxf(m0, lo32(s01));
                    m1 = fmaxf(m1, hi32(s01));
                    m2 = fmaxf(m2, lo32(s23));
                    m3 = fmaxf(m3, hi32(s23));
                }
                float best = fmaxf(fmaxf(m0, m1), fmaxf(m2, m3));
                // combine the 4 i-chunks within the thread-quad
                best = fmaxf(best, __shfl_xor_sync(0xffffffffu, best, 1));
                best = fmaxf(best, __shfl_xor_sync(0xffffffffu, best, 2));
                alpha = best + potv;

                if (c == 0) {
                    sb[(p ^ 1) * Cn + j] = alpha;
                    aout[(size_t)t * Cn] = alpha;
                }
                __syncthreads();
                p ^= 1;
            }
        }
    }

    // ---- Backward: warp 0 traces the path for this batch (transitions from smem) ----
    if (tid < 32) {
        const int l = tid;
        float* ob = out + (size_t)b * Tn;

        // last tag = argmax over alpha_{T-1} (currently in sb[p])
        const float4* sb4 = (const float4*)(sb + p * Cn);
        float4 av = sb4[l];
        int tag = warp_argmax4(av, l);
        if (l == 0) ob[Tn - 1] = (float)tag;

        const float4* arow = (const float4*)(g_alpha + (size_t)b * Tn * Cn);

        // Prefetch alpha rows 8 deep (independent of the tag chain)
        float4 pf[8];
        const int t0 = Tn - 2;
        #pragma unroll
        for (int u = 0; u < 8; ++u) {
            pf[u] = (t0 - u >= 0) ? arow[(size_t)(t0 - u) * 32 + l]
                                  : make_float4(0.f, 0.f, 0.f, 0.f);
        }

        for (int tb = t0; tb >= 0; tb -= 8) {
            #pragma unroll
            for (int u = 0; u < 8; ++u) {
                int t = tb - u;
                if (t >= 0) {
                    float4 a = pf[u];
                    if (t - 8 >= 0) pf[u] = arow[(size_t)(t - 8) * 32 + l];

                    // column 'tag' of transitions, from smem (29cyc instead of ~240cyc L2)
                    const float4* trow = (const float4*)(tT + tag * TSTRIDE);
                    float4 tv = trow[l];
                    float4 s;
                    s.x = a.x + tv.x;
                    s.y = a.y + tv.y;
                    s.z = a.z + tv.z;
                    s.w = a.w + tv.w;
                    tag = warp_argmax4(s, l);
                    if (l == 0) ob[t] = (float)tag;
                }
            }
        }
    }
}

extern "C" void kernel_launch(void* const* d_in, const int* in_sizes, int n_in,
                              void* d_out, int out_size) {
    const float* inputs = (const float*)d_in[0];       // [B, T, C] f32
    const float* transitions = (const float*)d_in[1];  // [C, C] f32
    float* out = (float*)d_out;                        // [B, T] f32 (tags)

    const int smem_bytes = (Cn * TSTRIDE + 2 * Cn) * (int)sizeof(float);  // ~68.6KB
    cudaFuncSetAttribute(viterbi_kernel, cudaFuncAttributeMaxDynamicSharedMemorySize, smem_bytes);
    viterbi_kernel<<<Bn, NTHR, smem_bytes>>>(inputs, transitions, out);
}